// round 13
// baseline (speedup 1.0000x reference)
#include <cuda_runtime.h>
#include <math.h>

// Fixed shapes for BlurredMem_61950608278069
#define BS 128
#define W  256
#define N  2048
#define R  4
#define EPSF 1e-8f
#define TB 8                  // blocks per team
#define TEAMS 32
#define REPS 4                // batches per team (32*4 = 128)

// Output layout: m_read (BS,R,W) | M_new (BS,W,N) | read_wt (BS,R,N)
#define OFF_MNEW (BS*R*W)
#define OFF_RWT  (BS*R*W + BS*W*N)

typedef unsigned long long u64;

// -------- packed f32x2 helpers (Blackwell; ptxas never auto-fuses these) ---
__device__ __forceinline__ u64 pk2(float v) {
    u64 r; asm("mov.b64 %0, {%1,%1};" : "=l"(r) : "f"(v)); return r;
}
__device__ __forceinline__ u64 fma2(u64 a, u64 b, u64 c) {
    u64 d; asm("fma.rn.f32x2 %0, %1, %2, %3;" : "=l"(d) : "l"(a), "l"(b), "l"(c));
    return d;
}
__device__ __forceinline__ u64 mul2(u64 a, u64 b) {
    u64 d; asm("mul.rn.f32x2 %0, %1, %2;" : "=l"(d) : "l"(a), "l"(b));
    return d;
}
__device__ __forceinline__ float2 up2(u64 p) {
    float2 f; asm("mov.b64 {%0, %1}, %2;" : "=f"(f.x), "=f"(f.y) : "l"(p));
    return f;
}
__device__ __forceinline__ float hadd2(u64 p) { float2 f = up2(p); return f.x + f.y; }

union V2 { ulonglong2 u; float4 f; };

// -------- scratch (device globals) --------
__device__ float  g_wk[BS*W];        // unnormalized write key (relu'd)
__device__ float2 g_wmer[BS*W];      // (write_m, erase_vec)
__device__ float4 g_kn4[BS*W];       // normalized read keys (r packed)
__device__ float  g_scal[BS*8];      // {Swm, C0..C3}
__device__ float  g_ZwP[BS*TB];      // per-member partial Zw
__device__ float4 g_ZrP[BS*TB];      // per-member partial Zr (4 heads)
__device__ float  g_wwt[BS*N];       // normalized write weights
__device__ float  g_rexp[BS*R*N];    // unnormalized read weights
__device__ int    g_cnt1[BS];        // team barrier counters (zeroed by k1)
__device__ int    g_cnt2[BS];

// -------- block reduction: warp shuffles + one smem pass (256 threads) ----
template<int NV>
__device__ __forceinline__ void blk_reduce_sum(float (&v)[NV], float* sbuf) {
    const int lane = threadIdx.x & 31, wid = threadIdx.x >> 5;
    #pragma unroll
    for (int i = 0; i < NV; i++) {
        float x = v[i];
        #pragma unroll
        for (int o = 16; o; o >>= 1) x += __shfl_xor_sync(0xffffffffu, x, o);
        if (lane == 0) sbuf[i*8 + wid] = x;
    }
    __syncthreads();
    #pragma unroll
    for (int i = 0; i < NV; i++) {
        float s = 0.f;
        #pragma unroll
        for (int j = 0; j < 8; j++) s += sbuf[i*8 + j];
        v[i] = s;
    }
    __syncthreads();
}

// -------- team barrier: release-fence + counter, t0 spins, acquire-fence --
__device__ __forceinline__ void team_sync(int* cnt) {
    __syncthreads();
    __threadfence();
    if (threadIdx.x == 0) {
        atomicAdd(cnt, 1);
        volatile int* vc = (volatile int*)cnt;
        while (*vc < TB) __nanosleep(64);
    }
    __syncthreads();
    __threadfence();
}

// ===================== K1: per-batch prep (grid 8 x BS) =====================
__global__ void k1_prep(const float* __restrict__ k_r, const float* __restrict__ m_t,
                        const float* __restrict__ e_t, const float* __restrict__ m_er,
                        const float* __restrict__ gW,  const float* __restrict__ gb,
                        const float* __restrict__ oW,  const float* __restrict__ ob) {
    __shared__ float sbuf[96];
    __shared__ __align__(16) float s_cat[2*W];
    const int b = blockIdx.y, t = threadIdx.x;

    if (blockIdx.x == 0 && t == 0) { g_cnt1[b] = 0; g_cnt2[b] = 0; }

    const float wm = tanhf(m_t[b*W + t]);
    const float me = m_er[b*W + t];
    const float ex = __expf(e_t[b*W + t]);          // erase softmax, no max pass

    float kv[R];
    #pragma unroll
    for (int r = 0; r < R; r++) kv[r] = tanhf(k_r[(b*R + r)*W + t]);

    // one fused reduction: {esum, gate, |kv|^2 x4, Swm, kv.wm x4}
    float v[11];
    v[0] = ex;
    v[1] = wm * gW[t] + me * gW[W + t];
    #pragma unroll
    for (int r = 0; r < R; r++) v[2+r] = kv[r] * kv[r];
    v[6] = wm * wm;
    #pragma unroll
    for (int r = 0; r < R; r++) v[7+r] = kv[r] * wm;
    blk_reduce_sum<11>(v, sbuf);

    const float g = 1.f / (1.f + __expf(-(v[1] + gb[0])));
    s_cat[t]     = g * wm;
    s_cat[W + t] = (1.f - g) * me;

    if (blockIdx.x == 0) {
        g_wmer[b*W + t] = make_float2(wm, ex / v[0]);
        float kn[R];
        #pragma unroll
        for (int r = 0; r < R; r++) kn[r] = kv[r] / (sqrtf(v[2+r]) + EPSF);
        g_kn4[b*W + t] = make_float4(kn[0], kn[1], kn[2], kn[3]);
        if (t == 0) {
            g_scal[b*8 + 0] = v[6];
            #pragma unroll
            for (int r = 0; r < R; r++)
                g_scal[b*8 + 1 + r] = v[7+r] / (sqrtf(v[2+r]) + EPSF);
        }
    }
    __syncthreads();

    // MLP: 32 rows per block, 8 threads per row
    const int o = blockIdx.x * 32 + (t >> 3);
    const int p = t & 7;
    const float4* orow4 = (const float4*)(oW + (size_t)o * 2 * W);
    const float4* sc4   = (const float4*)s_cat;
    float acc = 0.f;
    #pragma unroll
    for (int i = 0; i < 16; i++) {
        const int j = 8*i + p;
        float4 ow = orow4[j], sc = sc4[j];
        acc += ow.x*sc.x + ow.y*sc.y + ow.z*sc.z + ow.w*sc.w;
    }
    acc += __shfl_xor_sync(0xffffffffu, acc, 1);
    acc += __shfl_xor_sync(0xffffffffu, acc, 2);
    acc += __shfl_xor_sync(0xffffffffu, acc, 4);
    if (p == 0) g_wk[b*W + o] = fmaxf(acc + ob[o], 0.f);
}

// ===================== Fused persistent kernel =============================
// 256 blocks = 32 teams x 8 members, all co-resident (2/SM of 148 SMs).
// Team processes 4 batches sequentially; per batch: P1 moments (member's
// 256-column slice, f32x2), team barrier, P2 wwt/e/Zr from registers, team
// barrier, P3 stream over member's 32 w-rows with mem re-read hitting L2.
__global__ void __launch_bounds__(256, 2)
k_fused(const float* __restrict__ mem, float* __restrict__ Mnew,
        float* __restrict__ rwt, float* __restrict__ mread) {
    __shared__ __align__(16) char s_raw[40960];
    __shared__ float sbuf[32];
    const int t = threadIdx.x, lane = t & 31, wi = t >> 5;
    const int team = blockIdx.x >> 3, m = blockIdx.x & 7;

    // P1/P2 view of smem
    ulonglong2* s_knA = (ulonglong2*)(s_raw);          // [256] 4KB
    ulonglong2* s_knB = (ulonglong2*)(s_raw + 4096);   // [256] 4KB
    ulonglong2* s_ewm = (ulonglong2*)(s_raw + 8192);   // [256] 4KB
    u64*        s_wkn = (u64*)(s_raw + 12288);         // [256] 2KB
    // P3 view of smem (reused after team barrier 2)
    float* s_wwt = (float*)(s_raw);                    // [2048] 8KB
    float* s_e   = (float*)(s_raw + 8192);             // [4][2048] 32KB

    for (int rep = 0; rep < REPS; rep++) {
        const int b = team * REPS + rep;
        __syncthreads();   // protect smem reuse across reps

        // ---- prologue: per-batch tables + write-key normalization ----
        const float wk = g_wk[b*W + t];
        float v1[1] = { wk * wk };
        blk_reduce_sum<1>(v1, sbuf);
        const float wkn = wk / (sqrtf(v1[0]) + EPSF);
        const float2 meb = g_wmer[b*W + t];            // (wm, er)
        const float4 knb = g_kn4[b*W + t];
        s_knA[t] = make_ulonglong2(pk2(knb.x), pk2(knb.y));
        s_knB[t] = make_ulonglong2(pk2(knb.z), pk2(knb.w));
        s_ewm[t] = make_ulonglong2(pk2(meb.y), pk2(meb.x));
        s_wkn[t] = pk2(wkn);
        __syncthreads();

        // ---- P1: column moments (threads 0..127, 2 adjacent cols each) ----
        const int n0 = m * 256 + 2 * (t & 127);
        u64 S0=0,S1=0,S2=0,T0=0,T1=0,dW=0;
        u64 A0=0,A1=0,A2=0,A3=0,B0=0,B1=0,B2=0,B3=0;
        if (t < 128) {
            const u64* mp = (const u64*)(mem + (size_t)b * W * N + n0);
            #pragma unroll 16
            for (int w = 0; w < W; w++) {
                const u64 v = mp[(size_t)w * (N/2)];
                const ulonglong2 ka = s_knA[w];
                const ulonglong2 kb = s_knB[w];
                const ulonglong2 ew = s_ewm[w];        // {er2, wm2}
                const u64 u = mul2(ew.x, v);           // er * v
                S0 = fma2(v, v, S0);
                S1 = fma2(u, v, S1);
                S2 = fma2(u, u, S2);
                dW = fma2(s_wkn[w], v, dW);
                T0 = fma2(ew.y, v, T0);
                T1 = fma2(ew.y, u, T1);
                A0 = fma2(ka.x, v, A0);  A1 = fma2(ka.y, v, A1);
                A2 = fma2(kb.x, v, A2);  A3 = fma2(kb.y, v, A3);
                B0 = fma2(ka.x, u, B0);  B1 = fma2(ka.y, u, B1);
                B2 = fma2(kb.x, u, B2);  B3 = fma2(kb.y, u, B3);
            }
        }
        // epilogue in floats (zeros for t>=128)
        const float Swm = g_scal[b*8 + 0];
        const float Cs[R] = { g_scal[b*8+1], g_scal[b*8+2],
                              g_scal[b*8+3], g_scal[b*8+4] };
        const float2 sa = up2(S0), dw = up2(dW);
        const float2 s1 = up2(S1), s2 = up2(S2);
        const float2 t0 = up2(T0), t1 = up2(T1);
        float2 ew2 = make_float2(0.f, 0.f);
        if (t < 128) {
            ew2.x = __expf(-dw.x / (sqrtf(sa.x) + EPSF));
            ew2.y = __expf(-dw.y / (sqrtf(sa.y) + EPSF));
        }
        const float2 SB = make_float2(t0.x - s1.x, t0.y - s1.y);
        const float2 SC = make_float2(s2.x - 2.f*t1.x + Swm,
                                      s2.y - 2.f*t1.y + Swm);
        float2 Af[R] = { up2(A0), up2(A1), up2(A2), up2(A3) };
        float2 Bf[R] = { up2(B0), up2(B1), up2(B2), up2(B3) };

        float z1[1] = { ew2.x + ew2.y };
        blk_reduce_sum<1>(z1, sbuf);
        if (t == 0) g_ZwP[b*TB + m] = z1[0];
        team_sync(&g_cnt1[b]);

        // ---- P2: wwt + read-weight exponentials (threads 0..127) ----
        float Zw = 0.f;
        #pragma unroll
        for (int k = 0; k < TB; k++) Zw += g_ZwP[b*TB + k];
        const float iZw = 1.f / Zw;

        float zr[R] = {0.f, 0.f, 0.f, 0.f};
        if (t < 128) {
            const float2 wwt2 = make_float2(ew2.x * iZw, ew2.y * iZw);
            *(float2*)&g_wwt[(size_t)b*N + n0] = wwt2;
            const float nm2x = fmaf(wwt2.x, fmaf(wwt2.x, SC.x, 2.f*SB.x), sa.x);
            const float nm2y = fmaf(wwt2.y, fmaf(wwt2.y, SC.y, 2.f*SB.y), sa.y);
            const float invx = 1.f / (sqrtf(fmaxf(nm2x, 0.f)) + EPSF);
            const float invy = 1.f / (sqrtf(fmaxf(nm2y, 0.f)) + EPSF);
            #pragma unroll
            for (int r = 0; r < R; r++) {
                const float ex2 = __expf(fmaf(wwt2.x, Cs[r] - Bf[r].x, Af[r].x) * invx);
                const float ey2 = __expf(fmaf(wwt2.y, Cs[r] - Bf[r].y, Af[r].y) * invy);
                *(float2*)&g_rexp[((size_t)b*R + r)*N + n0] = make_float2(ex2, ey2);
                zr[r] = ex2 + ey2;
            }
        }
        blk_reduce_sum<R>(zr, sbuf);
        if (t == 0) g_ZrP[b*TB + m] = make_float4(zr[0], zr[1], zr[2], zr[3]);
        team_sync(&g_cnt2[b]);

        // ---- P3: stage + stream (all 256 threads; smem view switches) ----
        float Zr[R] = {0.f, 0.f, 0.f, 0.f};
        #pragma unroll
        for (int k = 0; k < TB; k++) {
            float4 zz = g_ZrP[b*TB + k];
            Zr[0] += zz.x; Zr[1] += zz.y; Zr[2] += zz.z; Zr[3] += zz.w;
        }

        #pragma unroll
        for (int k = 0; k < 2; k++) {
            const int idx = t + k * 256;
            ((float4*)s_wwt)[idx] = ((const float4*)(g_wwt + (size_t)b*N))[idx];
            #pragma unroll
            for (int r = 0; r < R; r++)
                ((float4*)(s_e + r*N))[idx] =
                    ((const float4*)(g_rexp + ((size_t)b*R + r)*N))[idx];
        }
        __syncthreads();

        // normalized rwt output slice (256 of 2048 float4)
        {
            const int idx = m * 256 + t;
            const int r = idx >> 9;
            const float s = 1.f / Zr[r];
            float4 vv = ((const float4*)s_e)[idx];
            vv.x *= s; vv.y *= s; vv.z *= s; vv.w *= s;
            ((float4*)(rwt + (size_t)b * R * N))[idx] = vv;
        }

        const int w0 = m * 32 + wi * 4;
        u64 wm2[4], ner2[4];
        #pragma unroll
        for (int row = 0; row < 4; row++) {
            float2 me2 = g_wmer[b*W + w0 + row];
            wm2[row]  = pk2(me2.x);
            ner2[row] = pk2(-me2.y);
        }

        const ulonglong2* mp = (const ulonglong2*)(mem  + ((size_t)b*W + w0) * N);
        ulonglong2*       op = (ulonglong2*)(Mnew + ((size_t)b*W + w0) * N);
        const ulonglong2* sw = (const ulonglong2*)s_wwt;
        const ulonglong2* se0 = (const ulonglong2*)(s_e);
        const ulonglong2* se1 = (const ulonglong2*)(s_e + N);
        const ulonglong2* se2 = (const ulonglong2*)(s_e + 2*N);
        const ulonglong2* se3 = (const ulonglong2*)(s_e + 3*N);

        u64 P[4][R] = {};
        ulonglong2 vc[4];
        #pragma unroll
        for (int row = 0; row < 4; row++) vc[row] = mp[lane + row * (N/4)];

        #pragma unroll 2
        for (int k = 0; k < 16; k++) {
            const int idx  = lane + k * 32;
            const int nidx = (k < 15) ? idx + 32 : idx;
            ulonglong2 vn[4];
            #pragma unroll
            for (int row = 0; row < 4; row++) vn[row] = mp[nidx + row * (N/4)];

            const ulonglong2 ww = sw[idx];
            const ulonglong2 e0 = se0[idx], e1 = se1[idx];
            const ulonglong2 e2 = se2[idx], e3 = se3[idx];
            #pragma unroll
            for (int row = 0; row < 4; row++) {
                const ulonglong2 v = vc[row];
                const u64 mna = fma2(wm2[row], ww.x, fma2(ner2[row], mul2(v.x, ww.x), v.x));
                const u64 mnb = fma2(wm2[row], ww.y, fma2(ner2[row], mul2(v.y, ww.y), v.y));
                V2 st; st.u = make_ulonglong2(mna, mnb);
                __stcs((float4*)&op[idx + row * (N/4)], st.f);
                P[row][0] = fma2(e0.x, mna, P[row][0]);
                P[row][0] = fma2(e0.y, mnb, P[row][0]);
                P[row][1] = fma2(e1.x, mna, P[row][1]);
                P[row][1] = fma2(e1.y, mnb, P[row][1]);
                P[row][2] = fma2(e2.x, mna, P[row][2]);
                P[row][2] = fma2(e2.y, mnb, P[row][2]);
                P[row][3] = fma2(e3.x, mna, P[row][3]);
                P[row][3] = fma2(e3.y, mnb, P[row][3]);
            }
            #pragma unroll
            for (int row = 0; row < 4; row++) vc[row] = vn[row];
        }

        #pragma unroll
        for (int row = 0; row < 4; row++) {
            #pragma unroll
            for (int r = 0; r < R; r++) {
                float s = hadd2(P[row][r]);
                #pragma unroll
                for (int o2 = 16; o2; o2 >>= 1)
                    s += __shfl_xor_sync(0xffffffffu, s, o2);
                if (lane == 0)
                    mread[(size_t)b*R*W + r*W + w0 + row] = s / Zr[r];
            }
        }
    }
}

// ===================== launch =====================
extern "C" void kernel_launch(void* const* d_in, const int* in_sizes, int n_in,
                              void* d_out, int out_size) {
    const float* k_r   = (const float*)d_in[0];
    const float* m_t   = (const float*)d_in[1];
    const float* e_t   = (const float*)d_in[2];
    const float* m_er  = (const float*)d_in[3];
    const float* mem   = (const float*)d_in[4];
    const float* gW    = (const float*)d_in[5];
    const float* gb    = (const float*)d_in[6];
    const float* oW    = (const float*)d_in[7];
    const float* ob    = (const float*)d_in[8];

    float* out   = (float*)d_out;
    float* mread = out;               // (BS,R,W)
    float* Mnew  = out + OFF_MNEW;    // (BS,W,N)
    float* rwt   = out + OFF_RWT;     // (BS,R,N)

    k1_prep<<<dim3(8, BS), 256>>>(k_r, m_t, e_t, m_er, gW, gb, oW, ob);
    k_fused<<<TEAMS * TB, 256>>>(mem, Mnew, rwt, mread);
}

// round 14
// speedup vs baseline: 1.0141x; 1.0141x over previous
#include <cuda_runtime.h>
#include <math.h>

// Fixed shapes for BlurredMem_61950608278069
#define BS 128
#define W  256
#define N  2048
#define R  4
#define EPSF 1e-8f
#define CHW 4                 // k2x n-chunks (512 n per block, 2 per thread)

// Output layout: m_read (BS,R,W) | M_new (BS,W,N) | read_wt (BS,R,N)
#define OFF_MNEW (BS*R*W)
#define OFF_RWT  (BS*R*W + BS*W*N)

// moment planes (per (b,n)) produced by k2x  (scalars pre-folded)
#define PL_EW 0               // exp(-cos) write weight numerator
#define PL_SA 1               // S0 = sum v^2
#define PL_SB 2               // T0 - S1
#define PL_SC 3               // S2 - 2*T1 + Swm
#define PL_A  4               // 4..7   A_r = sum kn_r * v
#define PL_D  8               // 8..11  D_r = C_r - B_r
#define NPL   12

typedef unsigned long long u64;

// -------- packed f32x2 helpers (Blackwell; ptxas never auto-fuses these) ---
__device__ __forceinline__ u64 pk2(float v) {
    u64 r; asm("mov.b64 %0, {%1,%1};" : "=l"(r) : "f"(v)); return r;
}
__device__ __forceinline__ u64 fma2(u64 a, u64 b, u64 c) {
    u64 d; asm("fma.rn.f32x2 %0, %1, %2, %3;" : "=l"(d) : "l"(a), "l"(b), "l"(c));
    return d;
}
__device__ __forceinline__ u64 mul2(u64 a, u64 b) {
    u64 d; asm("mul.rn.f32x2 %0, %1, %2;" : "=l"(d) : "l"(a), "l"(b));
    return d;
}
__device__ __forceinline__ float2 up2(u64 p) {
    float2 f; asm("mov.b64 {%0, %1}, %2;" : "=f"(f.x), "=f"(f.y) : "l"(p));
    return f;
}
__device__ __forceinline__ float hadd2(u64 p) { float2 f = up2(p); return f.x + f.y; }

union V2 { ulonglong2 u; float4 f; };

// -------- scratch (device globals) --------
__device__ float  g_wk[BS*W];        // unnormalized write key (relu'd)
__device__ float2 g_wmer[BS*W];      // (write_m, erase_vec)
__device__ float4 g_kn4[BS*W];       // normalized read keys (r packed)
__device__ float  g_mom[NPL*BS*N];   // per-column moments (12.6MB)
__device__ float  g_scal[BS*8];      // {Swm, C0..C3}
__device__ float  g_Zw_part[BS*CHW]; // per-block partial Zw
__device__ float  g_wwt[BS*N];       // normalized write weights
__device__ float  g_rexp[BS*R*N];    // unnormalized read weights (scratch)
__device__ float4 g_Zr_part[BS*8];   // per-chunk Zr (4 heads)

#define MOM(j) (g_mom + (size_t)(j)*BS*N)

// -------- block reduction: warp shuffles + one smem pass (256 threads) ----
template<int NV>
__device__ __forceinline__ void blk_reduce_sum(float (&v)[NV], float* sbuf) {
    const int lane = threadIdx.x & 31, wid = threadIdx.x >> 5;
    #pragma unroll
    for (int i = 0; i < NV; i++) {
        float x = v[i];
        #pragma unroll
        for (int o = 16; o; o >>= 1) x += __shfl_xor_sync(0xffffffffu, x, o);
        if (lane == 0) sbuf[i*8 + wid] = x;
    }
    __syncthreads();
    #pragma unroll
    for (int i = 0; i < NV; i++) {
        float s = 0.f;
        #pragma unroll
        for (int j = 0; j < 8; j++) s += sbuf[i*8 + j];
        v[i] = s;
    }
    __syncthreads();
}

// ===================== K1: per-batch prep (grid 8 x BS) =====================
__global__ void k1_prep(const float* __restrict__ k_r, const float* __restrict__ m_t,
                        const float* __restrict__ e_t, const float* __restrict__ m_er,
                        const float* __restrict__ gW,  const float* __restrict__ gb,
                        const float* __restrict__ oW,  const float* __restrict__ ob) {
    __shared__ float sbuf[96];
    __shared__ __align__(16) float s_cat[2*W];
    const int b = blockIdx.y, t = threadIdx.x;

    const float wm = tanhf(m_t[b*W + t]);
    const float me = m_er[b*W + t];
    const float ex = __expf(e_t[b*W + t]);          // erase softmax, no max pass

    float kv[R];
    #pragma unroll
    for (int r = 0; r < R; r++) kv[r] = tanhf(k_r[(b*R + r)*W + t]);

    // one fused reduction: {esum, gate, |kv|^2 x4, Swm, kv.wm x4}
    float v[11];
    v[0] = ex;
    v[1] = wm * gW[t] + me * gW[W + t];
    #pragma unroll
    for (int r = 0; r < R; r++) v[2+r] = kv[r] * kv[r];
    v[6] = wm * wm;
    #pragma unroll
    for (int r = 0; r < R; r++) v[7+r] = kv[r] * wm;
    blk_reduce_sum<11>(v, sbuf);

    const float g = 1.f / (1.f + __expf(-(v[1] + gb[0])));
    s_cat[t]     = g * wm;
    s_cat[W + t] = (1.f - g) * me;

    if (blockIdx.x == 0) {
        g_wmer[b*W + t] = make_float2(wm, ex / v[0]);
        float kn[R];
        #pragma unroll
        for (int r = 0; r < R; r++) kn[r] = kv[r] / (sqrtf(v[2+r]) + EPSF);
        g_kn4[b*W + t] = make_float4(kn[0], kn[1], kn[2], kn[3]);
        if (t == 0) {
            g_scal[b*8 + 0] = v[6];
            #pragma unroll
            for (int r = 0; r < R; r++)
                g_scal[b*8 + 1 + r] = v[7+r] / (sqrtf(v[2+r]) + EPSF);
        }
    }
    __syncthreads();

    // MLP: 32 rows per block, 8 threads per row
    const int o = blockIdx.x * 32 + (t >> 3);
    const int p = t & 7;
    const float4* orow4 = (const float4*)(oW + (size_t)o * 2 * W);
    const float4* sc4   = (const float4*)s_cat;
    float acc = 0.f;
    #pragma unroll
    for (int i = 0; i < 16; i++) {
        const int j = 8*i + p;
        float4 ow = orow4[j], sc = sc4[j];
        acc += ow.x*sc.x + ow.y*sc.y + ow.z*sc.z + ow.w*sc.w;
    }
    acc += __shfl_xor_sync(0xffffffffu, acc, 1);
    acc += __shfl_xor_sync(0xffffffffu, acc, 2);
    acc += __shfl_xor_sync(0xffffffffu, acc, 4);
    if (p == 0) g_wk[b*W + o] = fmaxf(acc + ob[o], 0.f);
}

// ===================== K2x: one pass over mem -> column moments (f32x2) ===
// Thread owns 2 adjacent columns. No launch bound (avoid accumulator
// spills); software prefetch depth 8 like k4x for latency hiding.
__global__ void
k2x_moments(const float* __restrict__ mem) {
    __shared__ __align__(16) ulonglong2 s_knA[W];   // {dup(kn0), dup(kn1)}
    __shared__ __align__(16) ulonglong2 s_knB[W];   // {dup(kn2), dup(kn3)}
    __shared__ __align__(16) ulonglong2 s_ewm[W];   // {dup(er),  dup(wm)}
    __shared__ u64  s_wkn[W];                       // dup(wkn)
    __shared__ float sbuf[8];
    const int b = blockIdx.y, t = threadIdx.x;

    // prologue: t == w  (write-key normalization)
    const float wk = g_wk[b*W + t];
    float v1[1] = { wk * wk };
    blk_reduce_sum<1>(v1, sbuf);
    const float wkn = wk / (sqrtf(v1[0]) + EPSF);
    const float2 me = g_wmer[b*W + t];              // (wm, er)
    const float4 kn = g_kn4[b*W + t];
    s_knA[t] = make_ulonglong2(pk2(kn.x), pk2(kn.y));
    s_knB[t] = make_ulonglong2(pk2(kn.z), pk2(kn.w));
    s_ewm[t] = make_ulonglong2(pk2(me.y), pk2(me.x));
    s_wkn[t] = pk2(wkn);
    __syncthreads();

    const int n0 = blockIdx.x * 512 + 2 * t;
    const u64* mp = (const u64*)(mem + (size_t)b * W * N + n0);

    u64 S0 = 0, S1 = 0, S2 = 0, T0 = 0, T1 = 0, dW = 0;
    u64 A0 = 0, A1 = 0, A2 = 0, A3 = 0;
    u64 B0 = 0, B1 = 0, B2 = 0, B3 = 0;

    u64 cur[8], nxt[8];
    #pragma unroll
    for (int i = 0; i < 8; i++) cur[i] = mp[(size_t)i * (N/2)];

    #pragma unroll 4
    for (int wb = 0; wb < W; wb += 8) {
        const u64* mpn = mp + (size_t)(wb + 8) * (N/2);
        if (wb + 8 < W) {
            #pragma unroll
            for (int i = 0; i < 8; i++) nxt[i] = mpn[(size_t)i * (N/2)];
        }
        #pragma unroll
        for (int i = 0; i < 8; i++) {
            const int w = wb + i;
            const u64 v = cur[i];
            const ulonglong2 ka = s_knA[w];
            const ulonglong2 kb = s_knB[w];
            const ulonglong2 ew = s_ewm[w];         // {er2, wm2}
            const u64 u = mul2(ew.x, v);            // er * v
            S0 = fma2(v, v, S0);
            S1 = fma2(u, v, S1);
            S2 = fma2(u, u, S2);
            dW = fma2(s_wkn[w], v, dW);
            T0 = fma2(ew.y, v, T0);
            T1 = fma2(ew.y, u, T1);
            A0 = fma2(ka.x, v, A0);  A1 = fma2(ka.y, v, A1);
            A2 = fma2(kb.x, v, A2);  A3 = fma2(kb.y, v, A3);
            B0 = fma2(ka.x, u, B0);  B1 = fma2(ka.y, u, B1);
            B2 = fma2(kb.x, u, B2);  B3 = fma2(kb.y, u, B3);
        }
        if (wb + 8 < W) {
            #pragma unroll
            for (int i = 0; i < 8; i++) cur[i] = nxt[i];
        }
    }

    const float Swm = g_scal[b*8 + 0];
    const float C0 = g_scal[b*8+1], C1 = g_scal[b*8+2];
    const float C2 = g_scal[b*8+3], C3 = g_scal[b*8+4];

    const float2 s0 = up2(S0), dw = up2(dW);
    const float2 s1 = up2(S1), s2 = up2(S2);
    const float2 t0 = up2(T0), t1 = up2(T1);
    float2 ew2;
    ew2.x = __expf(-dw.x / (sqrtf(s0.x) + EPSF));
    ew2.y = __expf(-dw.y / (sqrtf(s0.y) + EPSF));

    const size_t o = (size_t)b * N + n0;
    *(float2*)&MOM(PL_EW)[o] = ew2;
    *(float2*)&MOM(PL_SA)[o] = s0;
    *(float2*)&MOM(PL_SB)[o] = make_float2(t0.x - s1.x, t0.y - s1.y);
    *(float2*)&MOM(PL_SC)[o] = make_float2(s2.x - 2.f*t1.x + Swm,
                                           s2.y - 2.f*t1.y + Swm);
    float2 b0 = up2(B0), b1 = up2(B1), b2 = up2(B2), b3 = up2(B3);
    *(float2*)&MOM(PL_A+0)[o] = up2(A0);
    *(float2*)&MOM(PL_A+1)[o] = up2(A1);
    *(float2*)&MOM(PL_A+2)[o] = up2(A2);
    *(float2*)&MOM(PL_A+3)[o] = up2(A3);
    *(float2*)&MOM(PL_D+0)[o] = make_float2(C0 - b0.x, C0 - b0.y);
    *(float2*)&MOM(PL_D+1)[o] = make_float2(C1 - b1.x, C1 - b1.y);
    *(float2*)&MOM(PL_D+2)[o] = make_float2(C2 - b2.x, C2 - b2.y);
    *(float2*)&MOM(PL_D+3)[o] = make_float2(C3 - b3.x, C3 - b3.y);

    float z[1] = { ew2.x + ew2.y };
    blk_reduce_sum<1>(z, sbuf);
    if (t == 0) g_Zw_part[b*CHW + blockIdx.x] = z[0];
}

// ===================== K3x: per-column read weights from folded moments ===
__global__ void k3x_logits() {
    __shared__ float sbuf[32];
    const int b = blockIdx.y, t = threadIdx.x;
    const int n = blockIdx.x * 256 + t;
    const size_t o = (size_t)b * N + n;

    float Zw = 0.f;
    #pragma unroll
    for (int k = 0; k < CHW; k++) Zw += g_Zw_part[b*CHW + k];

    const float wwt = MOM(PL_EW)[o] / Zw;
    g_wwt[o] = wwt;

    const float Sa = MOM(PL_SA)[o];
    const float Sb = MOM(PL_SB)[o];
    const float Sc = MOM(PL_SC)[o];
    const float nm2 = fmaf(wwt, fmaf(wwt, Sc, 2.f * Sb), Sa);
    const float inv = 1.f / (sqrtf(fmaxf(nm2, 0.f)) + EPSF);

    float e4[R];
    #pragma unroll
    for (int r = 0; r < R; r++) {
        const float Ar = MOM(PL_A+r)[o];
        const float Dr = MOM(PL_D+r)[o];
        e4[r] = __expf(fmaf(wwt, Dr, Ar) * inv);
        g_rexp[((size_t)b*R + r)*N + n] = e4[r];
    }
    blk_reduce_sum<R>(e4, sbuf);
    if (t == 0)
        g_Zr_part[b*8 + blockIdx.x] = make_float4(e4[0], e4[1], e4[2], e4[3]);
}

// ===================== K4x: M_new stream + m_read + normalized rwt ========
// grid (8, BS); warp owns 4 w-rows. Stages wwt + e (full batch) in smem;
// writes its normalized rwt output slice; streams mem, writes M_new,
// accumulates P[row][r] += e_r * mn in packed registers.
__global__ void __launch_bounds__(256, 2)
k4x_stream(const float* __restrict__ mem, float* __restrict__ Mnew,
           float* __restrict__ rwt, float* __restrict__ mread) {
    __shared__ __align__(16) float s_wwt[N];      // 8 KB
    __shared__ __align__(16) float s_e[R][N];     // 32 KB
    const int b = blockIdx.y, c = blockIdx.x;
    const int t = threadIdx.x, lane = t & 31, wi = t >> 5;

    float Zr[R] = {0,0,0,0};
    #pragma unroll
    for (int k = 0; k < 8; k++) {
        float4 z = g_Zr_part[b*8 + k];
        Zr[0] += z.x; Zr[1] += z.y; Zr[2] += z.z; Zr[3] += z.w;
    }

    #pragma unroll
    for (int k = 0; k < 2; k++) {
        const int idx = t + k * 256;
        ((float4*)s_wwt)[idx] = ((const float4*)(g_wwt + (size_t)b*N))[idx];
        #pragma unroll
        for (int r = 0; r < R; r++)
            ((float4*)&s_e[r][0])[idx] =
                ((const float4*)(g_rexp + ((size_t)b*R + r)*N))[idx];
    }
    __syncthreads();

    // write this block's normalized rwt output slice (256 of 2048 float4)
    {
        const int idx = c * 256 + t;
        const int r = idx >> 9;
        const float s = 1.f / Zr[r];
        float4 v = ((const float4*)s_e)[idx];
        v.x *= s; v.y *= s; v.z *= s; v.w *= s;
        ((float4*)(rwt + (size_t)b * R * N))[idx] = v;
    }

    const int w0 = c * 32 + wi * 4;
    u64 wm2[4], ner2[4];
    #pragma unroll
    for (int row = 0; row < 4; row++) {
        float2 me = g_wmer[b*W + w0 + row];
        wm2[row]  = pk2(me.x);
        ner2[row] = pk2(-me.y);
    }

    const ulonglong2* mp = (const ulonglong2*)(mem  + ((size_t)b*W + w0) * N);
    ulonglong2*       op = (ulonglong2*)(Mnew + ((size_t)b*W + w0) * N);
    const ulonglong2* sw = (const ulonglong2*)s_wwt;
    const ulonglong2* se0 = (const ulonglong2*)&s_e[0][0];
    const ulonglong2* se1 = (const ulonglong2*)&s_e[1][0];
    const ulonglong2* se2 = (const ulonglong2*)&s_e[2][0];
    const ulonglong2* se3 = (const ulonglong2*)&s_e[3][0];

    u64 P[4][R] = {};
    ulonglong2 vc[4];
    #pragma unroll
    for (int row = 0; row < 4; row++) vc[row] = mp[lane + row * (N/4)];

    #pragma unroll 2
    for (int k = 0; k < 16; k++) {
        const int idx  = lane + k * 32;
        const int nidx = (k < 15) ? idx + 32 : idx;
        ulonglong2 vn[4];
        #pragma unroll
        for (int row = 0; row < 4; row++) vn[row] = mp[nidx + row * (N/4)];

        const ulonglong2 ww = sw[idx];
        const ulonglong2 e0 = se0[idx], e1 = se1[idx];
        const ulonglong2 e2 = se2[idx], e3 = se3[idx];
        #pragma unroll
        for (int row = 0; row < 4; row++) {
            const ulonglong2 v = vc[row];
            // mn = wm*ww + (-er)*(v*ww) + v
            const u64 mna = fma2(wm2[row], ww.x, fma2(ner2[row], mul2(v.x, ww.x), v.x));
            const u64 mnb = fma2(wm2[row], ww.y, fma2(ner2[row], mul2(v.y, ww.y), v.y));
            V2 st; st.u = make_ulonglong2(mna, mnb);
            __stcs((float4*)&op[idx + row * (N/4)], st.f);
            P[row][0] = fma2(e0.x, mna, P[row][0]);
            P[row][0] = fma2(e0.y, mnb, P[row][0]);
            P[row][1] = fma2(e1.x, mna, P[row][1]);
            P[row][1] = fma2(e1.y, mnb, P[row][1]);
            P[row][2] = fma2(e2.x, mna, P[row][2]);
            P[row][2] = fma2(e2.y, mnb, P[row][2]);
            P[row][3] = fma2(e3.x, mna, P[row][3]);
            P[row][3] = fma2(e3.y, mnb, P[row][3]);
        }
        #pragma unroll
        for (int row = 0; row < 4; row++) vc[row] = vn[row];
    }

    // reduce packed accumulators and write m_read
    #pragma unroll
    for (int row = 0; row < 4; row++) {
        #pragma unroll
        for (int r = 0; r < R; r++) {
            float s = hadd2(P[row][r]);
            #pragma unroll
            for (int o2 = 16; o2; o2 >>= 1)
                s += __shfl_xor_sync(0xffffffffu, s, o2);
            if (lane == 0)
                mread[(size_t)b*R*W + r*W + w0 + row] = s / Zr[r];
        }
    }
}

// ===================== launch =====================
extern "C" void kernel_launch(void* const* d_in, const int* in_sizes, int n_in,
                              void* d_out, int out_size) {
    const float* k_r   = (const float*)d_in[0];
    const float* m_t   = (const float*)d_in[1];
    const float* e_t   = (const float*)d_in[2];
    const float* m_er  = (const float*)d_in[3];
    const float* mem   = (const float*)d_in[4];
    const float* gW    = (const float*)d_in[5];
    const float* gb    = (const float*)d_in[6];
    const float* oW    = (const float*)d_in[7];
    const float* ob    = (const float*)d_in[8];

    float* out   = (float*)d_out;
    float* mread = out;               // (BS,R,W)
    float* Mnew  = out + OFF_MNEW;    // (BS,W,N)
    float* rwt   = out + OFF_RWT;     // (BS,R,N)

    k1_prep    <<<dim3(8,   BS), 256>>>(k_r, m_t, e_t, m_er, gW, gb, oW, ob);
    k2x_moments<<<dim3(CHW, BS), 256>>>(mem);
    k3x_logits <<<dim3(8,   BS), 256>>>();
    k4x_stream <<<dim3(8,   BS), 256>>>(mem, Mnew, rwt, mread);
}

// round 15
// speedup vs baseline: 1.0214x; 1.0072x over previous
#include <cuda_runtime.h>
#include <math.h>

// Fixed shapes for BlurredMem_61950608278069
#define BS 128
#define W  256
#define N  2048
#define R  4
#define EPSF 1e-8f
#define CHW 4                 // k23 n-chunks (512 n per block, 2 per thread)

// Output layout: m_read (BS,R,W) | M_new (BS,W,N) | read_wt (BS,R,N)
#define OFF_MNEW (BS*R*W)
#define OFF_RWT  (BS*R*W + BS*W*N)

typedef unsigned long long u64;

// -------- packed f32x2 helpers (Blackwell; ptxas never auto-fuses these) ---
__device__ __forceinline__ u64 pk2(float v) {
    u64 r; asm("mov.b64 %0, {%1,%1};" : "=l"(r) : "f"(v)); return r;
}
__device__ __forceinline__ u64 fma2(u64 a, u64 b, u64 c) {
    u64 d; asm("fma.rn.f32x2 %0, %1, %2, %3;" : "=l"(d) : "l"(a), "l"(b), "l"(c));
    return d;
}
__device__ __forceinline__ u64 mul2(u64 a, u64 b) {
    u64 d; asm("mul.rn.f32x2 %0, %1, %2;" : "=l"(d) : "l"(a), "l"(b));
    return d;
}
__device__ __forceinline__ float2 up2(u64 p) {
    float2 f; asm("mov.b64 {%0, %1}, %2;" : "=f"(f.x), "=f"(f.y) : "l"(p));
    return f;
}
__device__ __forceinline__ float hadd2(u64 p) { float2 f = up2(p); return f.x + f.y; }

union V2 { ulonglong2 u; float4 f; };

// -------- scratch (device globals) --------
__device__ float  g_wk[BS*W];        // unnormalized write key (relu'd)
__device__ float2 g_wmer[BS*W];      // (write_m, erase_vec)
__device__ float4 g_kn4[BS*W];       // normalized read keys (r packed)
__device__ float  g_scal[BS*8];      // {Swm, C0..C3}
__device__ float  g_Zw_part[BS*CHW]; // per-block partial Zw
__device__ float  g_wwt[BS*N];       // normalized write weights
__device__ float  g_rexp[BS*R*N];    // unnormalized read weights (scratch)
__device__ float4 g_Zr_part[BS*CHW]; // per-chunk Zr (4 heads)
__device__ int    g_cnt[BS];         // per-batch barrier counters (k1 zeroes)

// -------- block reduction: warp shuffles + one smem pass (256 threads) ----
template<int NV>
__device__ __forceinline__ void blk_reduce_sum(float (&v)[NV], float* sbuf) {
    const int lane = threadIdx.x & 31, wid = threadIdx.x >> 5;
    #pragma unroll
    for (int i = 0; i < NV; i++) {
        float x = v[i];
        #pragma unroll
        for (int o = 16; o; o >>= 1) x += __shfl_xor_sync(0xffffffffu, x, o);
        if (lane == 0) sbuf[i*8 + wid] = x;
    }
    __syncthreads();
    #pragma unroll
    for (int i = 0; i < NV; i++) {
        float s = 0.f;
        #pragma unroll
        for (int j = 0; j < 8; j++) s += sbuf[i*8 + j];
        v[i] = s;
    }
    __syncthreads();
}

// -------- 4-block batch barrier: release + counter, t0 spins, acquire -----
__device__ __forceinline__ void team_sync4(int* cnt) {
    __syncthreads();
    __threadfence();
    if (threadIdx.x == 0) {
        atomicAdd(cnt, 1);
        volatile int* vc = (volatile int*)cnt;
        while (*vc < CHW) __nanosleep(64);
    }
    __syncthreads();
    __threadfence();
}

// ===================== K1: per-batch prep (grid 8 x BS) =====================
__global__ void k1_prep(const float* __restrict__ k_r, const float* __restrict__ m_t,
                        const float* __restrict__ e_t, const float* __restrict__ m_er,
                        const float* __restrict__ gW,  const float* __restrict__ gb,
                        const float* __restrict__ oW,  const float* __restrict__ ob) {
    __shared__ float sbuf[96];
    __shared__ __align__(16) float s_cat[2*W];
    const int b = blockIdx.y, t = threadIdx.x;

    if (blockIdx.x == 0 && t == 0) g_cnt[b] = 0;   // reset barrier counter

    const float wm = tanhf(m_t[b*W + t]);
    const float me = m_er[b*W + t];
    const float ex = __expf(e_t[b*W + t]);          // erase softmax, no max pass

    float kv[R];
    #pragma unroll
    for (int r = 0; r < R; r++) kv[r] = tanhf(k_r[(b*R + r)*W + t]);

    // one fused reduction: {esum, gate, |kv|^2 x4, Swm, kv.wm x4}
    float v[11];
    v[0] = ex;
    v[1] = wm * gW[t] + me * gW[W + t];
    #pragma unroll
    for (int r = 0; r < R; r++) v[2+r] = kv[r] * kv[r];
    v[6] = wm * wm;
    #pragma unroll
    for (int r = 0; r < R; r++) v[7+r] = kv[r] * wm;
    blk_reduce_sum<11>(v, sbuf);

    const float g = 1.f / (1.f + __expf(-(v[1] + gb[0])));
    s_cat[t]     = g * wm;
    s_cat[W + t] = (1.f - g) * me;

    if (blockIdx.x == 0) {
        g_wmer[b*W + t] = make_float2(wm, ex / v[0]);
        float kn[R];
        #pragma unroll
        for (int r = 0; r < R; r++) kn[r] = kv[r] / (sqrtf(v[2+r]) + EPSF);
        g_kn4[b*W + t] = make_float4(kn[0], kn[1], kn[2], kn[3]);
        if (t == 0) {
            g_scal[b*8 + 0] = v[6];
            #pragma unroll
            for (int r = 0; r < R; r++)
                g_scal[b*8 + 1 + r] = v[7+r] / (sqrtf(v[2+r]) + EPSF);
        }
    }
    __syncthreads();

    // MLP: 32 rows per block, 8 threads per row
    const int o = blockIdx.x * 32 + (t >> 3);
    const int p = t & 7;
    const float4* orow4 = (const float4*)(oW + (size_t)o * 2 * W);
    const float4* sc4   = (const float4*)s_cat;
    float acc = 0.f;
    #pragma unroll
    for (int i = 0; i < 16; i++) {
        const int j = 8*i + p;
        float4 ow = orow4[j], sc = sc4[j];
        acc += ow.x*sc.x + ow.y*sc.y + ow.z*sc.z + ow.w*sc.w;
    }
    acc += __shfl_xor_sync(0xffffffffu, acc, 1);
    acc += __shfl_xor_sync(0xffffffffu, acc, 2);
    acc += __shfl_xor_sync(0xffffffffu, acc, 4);
    if (p == 0) g_wk[b*W + o] = fmaxf(acc + ob[o], 0.f);
}

// ===================== K23: moments + (barrier) + read weights =============
// Thread owns 2 adjacent columns; moments stay in registers. After the main
// loop, the batch's 4 blocks sync on a counter; each then computes wwt/e_r
// locally and writes only g_wwt + g_rexp + Zr partials. No moment planes.
__global__ void
k23_moments(const float* __restrict__ mem) {
    __shared__ __align__(16) ulonglong2 s_knA[W];   // {dup(kn0), dup(kn1)}
    __shared__ __align__(16) ulonglong2 s_knB[W];   // {dup(kn2), dup(kn3)}
    __shared__ __align__(16) ulonglong2 s_ewm[W];   // {dup(er),  dup(wm)}
    __shared__ u64  s_wkn[W];                       // dup(wkn)
    __shared__ float sbuf[32];
    const int b = blockIdx.y, t = threadIdx.x;

    // prologue: t == w  (write-key normalization)
    const float wk = g_wk[b*W + t];
    float v1[1] = { wk * wk };
    blk_reduce_sum<1>(v1, sbuf);
    const float wkn = wk / (sqrtf(v1[0]) + EPSF);
    const float2 me = g_wmer[b*W + t];              // (wm, er)
    const float4 kn = g_kn4[b*W + t];
    s_knA[t] = make_ulonglong2(pk2(kn.x), pk2(kn.y));
    s_knB[t] = make_ulonglong2(pk2(kn.z), pk2(kn.w));
    s_ewm[t] = make_ulonglong2(pk2(me.y), pk2(me.x));
    s_wkn[t] = pk2(wkn);
    __syncthreads();

    const int n0 = blockIdx.x * 512 + 2 * t;
    const u64* mp = (const u64*)(mem + (size_t)b * W * N + n0);

    u64 S0 = 0, S1 = 0, S2 = 0, T0 = 0, T1 = 0, dW = 0;
    u64 A0 = 0, A1 = 0, A2 = 0, A3 = 0;
    u64 B0 = 0, B1 = 0, B2 = 0, B3 = 0;

    u64 cur[8], nxt[8];
    #pragma unroll
    for (int i = 0; i < 8; i++) cur[i] = mp[(size_t)i * (N/2)];

    #pragma unroll 4
    for (int wb = 0; wb < W; wb += 8) {
        const u64* mpn = mp + (size_t)(wb + 8) * (N/2);
        if (wb + 8 < W) {
            #pragma unroll
            for (int i = 0; i < 8; i++) nxt[i] = mpn[(size_t)i * (N/2)];
        }
        #pragma unroll
        for (int i = 0; i < 8; i++) {
            const int w = wb + i;
            const u64 v = cur[i];
            const ulonglong2 ka = s_knA[w];
            const ulonglong2 kb = s_knB[w];
            const ulonglong2 ew = s_ewm[w];         // {er2, wm2}
            const u64 u = mul2(ew.x, v);            // er * v
            S0 = fma2(v, v, S0);
            S1 = fma2(u, v, S1);
            S2 = fma2(u, u, S2);
            dW = fma2(s_wkn[w], v, dW);
            T0 = fma2(ew.y, v, T0);
            T1 = fma2(ew.y, u, T1);
            A0 = fma2(ka.x, v, A0);  A1 = fma2(ka.y, v, A1);
            A2 = fma2(kb.x, v, A2);  A3 = fma2(kb.y, v, A3);
            B0 = fma2(ka.x, u, B0);  B1 = fma2(ka.y, u, B1);
            B2 = fma2(kb.x, u, B2);  B3 = fma2(kb.y, u, B3);
        }
        if (wb + 8 < W) {
            #pragma unroll
            for (int i = 0; i < 8; i++) cur[i] = nxt[i];
        }
    }

    // ---- fold scalars; everything stays in registers ----
    const float Swm = g_scal[b*8 + 0];
    const float Cs[R] = { g_scal[b*8+1], g_scal[b*8+2],
                          g_scal[b*8+3], g_scal[b*8+4] };

    const float2 sa = up2(S0), dw = up2(dW);
    const float2 s1 = up2(S1), s2 = up2(S2);
    const float2 t0 = up2(T0), t1 = up2(T1);
    float2 ew2;
    ew2.x = __expf(-dw.x / (sqrtf(sa.x) + EPSF));
    ew2.y = __expf(-dw.y / (sqrtf(sa.y) + EPSF));
    const float2 SB = make_float2(t0.x - s1.x, t0.y - s1.y);
    const float2 SC = make_float2(s2.x - 2.f*t1.x + Swm,
                                  s2.y - 2.f*t1.y + Swm);
    const float2 Af[R] = { up2(A0), up2(A1), up2(A2), up2(A3) };
    const float2 Bf[R] = { up2(B0), up2(B1), up2(B2), up2(B3) };

    // partial Zw, then batch barrier (4 sibling blocks)
    float z[1] = { ew2.x + ew2.y };
    blk_reduce_sum<1>(z, sbuf);
    if (t == 0) g_Zw_part[b*CHW + blockIdx.x] = z[0];
    team_sync4(&g_cnt[b]);

    float Zw = 0.f;
    #pragma unroll
    for (int k = 0; k < CHW; k++) Zw += g_Zw_part[b*CHW + k];
    const float iZw = 1.f / Zw;

    // wwt + read-weight exponentials for this thread's 2 columns
    const float2 wwt2 = make_float2(ew2.x * iZw, ew2.y * iZw);
    *(float2*)&g_wwt[(size_t)b*N + n0] = wwt2;

    const float nm2x = fmaf(wwt2.x, fmaf(wwt2.x, SC.x, 2.f*SB.x), sa.x);
    const float nm2y = fmaf(wwt2.y, fmaf(wwt2.y, SC.y, 2.f*SB.y), sa.y);
    const float invx = 1.f / (sqrtf(fmaxf(nm2x, 0.f)) + EPSF);
    const float invy = 1.f / (sqrtf(fmaxf(nm2y, 0.f)) + EPSF);

    float zr[R];
    #pragma unroll
    for (int r = 0; r < R; r++) {
        const float ex2 = __expf(fmaf(wwt2.x, Cs[r] - Bf[r].x, Af[r].x) * invx);
        const float ey2 = __expf(fmaf(wwt2.y, Cs[r] - Bf[r].y, Af[r].y) * invy);
        *(float2*)&g_rexp[((size_t)b*R + r)*N + n0] = make_float2(ex2, ey2);
        zr[r] = ex2 + ey2;
    }
    blk_reduce_sum<R>(zr, sbuf);
    if (t == 0)
        g_Zr_part[b*CHW + blockIdx.x] = make_float4(zr[0], zr[1], zr[2], zr[3]);
}

// ===================== K4x: M_new stream + m_read + normalized rwt ========
// grid (8, BS); warp owns 4 w-rows. Stages wwt + e (full batch) in smem;
// writes its normalized rwt output slice; streams mem, writes M_new,
// accumulates P[row][r] += e_r * mn in packed registers.
__global__ void __launch_bounds__(256, 2)
k4x_stream(const float* __restrict__ mem, float* __restrict__ Mnew,
           float* __restrict__ rwt, float* __restrict__ mread) {
    __shared__ __align__(16) float s_wwt[N];      // 8 KB
    __shared__ __align__(16) float s_e[R][N];     // 32 KB
    const int b = blockIdx.y, c = blockIdx.x;
    const int t = threadIdx.x, lane = t & 31, wi = t >> 5;

    float Zr[R] = {0,0,0,0};
    #pragma unroll
    for (int k = 0; k < CHW; k++) {
        float4 z = g_Zr_part[b*CHW + k];
        Zr[0] += z.x; Zr[1] += z.y; Zr[2] += z.z; Zr[3] += z.w;
    }

    #pragma unroll
    for (int k = 0; k < 2; k++) {
        const int idx = t + k * 256;
        ((float4*)s_wwt)[idx] = ((const float4*)(g_wwt + (size_t)b*N))[idx];
        #pragma unroll
        for (int r = 0; r < R; r++)
            ((float4*)&s_e[r][0])[idx] =
                ((const float4*)(g_rexp + ((size_t)b*R + r)*N))[idx];
    }
    __syncthreads();

    // write this block's normalized rwt output slice (256 of 2048 float4)
    {
        const int idx = c * 256 + t;
        const int r = idx >> 9;
        const float s = 1.f / Zr[r];
        float4 v = ((const float4*)s_e)[idx];
        v.x *= s; v.y *= s; v.z *= s; v.w *= s;
        ((float4*)(rwt + (size_t)b * R * N))[idx] = v;
    }

    const int w0 = c * 32 + wi * 4;
    u64 wm2[4], ner2[4];
    #pragma unroll
    for (int row = 0; row < 4; row++) {
        float2 me = g_wmer[b*W + w0 + row];
        wm2[row]  = pk2(me.x);
        ner2[row] = pk2(-me.y);
    }

    const ulonglong2* mp = (const ulonglong2*)(mem  + ((size_t)b*W + w0) * N);
    ulonglong2*       op = (ulonglong2*)(Mnew + ((size_t)b*W + w0) * N);
    const ulonglong2* sw = (const ulonglong2*)s_wwt;
    const ulonglong2* se0 = (const ulonglong2*)&s_e[0][0];
    const ulonglong2* se1 = (const ulonglong2*)&s_e[1][0];
    const ulonglong2* se2 = (const ulonglong2*)&s_e[2][0];
    const ulonglong2* se3 = (const ulonglong2*)&s_e[3][0];

    u64 P[4][R] = {};
    ulonglong2 vc[4];
    #pragma unroll
    for (int row = 0; row < 4; row++) vc[row] = mp[lane + row * (N/4)];

    #pragma unroll 2
    for (int k = 0; k < 16; k++) {
        const int idx  = lane + k * 32;
        const int nidx = (k < 15) ? idx + 32 : idx;
        ulonglong2 vn[4];
        #pragma unroll
        for (int row = 0; row < 4; row++) vn[row] = mp[nidx + row * (N/4)];

        const ulonglong2 ww = sw[idx];
        const ulonglong2 e0 = se0[idx], e1 = se1[idx];
        const ulonglong2 e2 = se2[idx], e3 = se3[idx];
        #pragma unroll
        for (int row = 0; row < 4; row++) {
            const ulonglong2 v = vc[row];
            // mn = wm*ww + (-er)*(v*ww) + v
            const u64 mna = fma2(wm2[row], ww.x, fma2(ner2[row], mul2(v.x, ww.x), v.x));
            const u64 mnb = fma2(wm2[row], ww.y, fma2(ner2[row], mul2(v.y, ww.y), v.y));
            V2 st; st.u = make_ulonglong2(mna, mnb);
            __stcs((float4*)&op[idx + row * (N/4)], st.f);
            P[row][0] = fma2(e0.x, mna, P[row][0]);
            P[row][0] = fma2(e0.y, mnb, P[row][0]);
            P[row][1] = fma2(e1.x, mna, P[row][1]);
            P[row][1] = fma2(e1.y, mnb, P[row][1]);
            P[row][2] = fma2(e2.x, mna, P[row][2]);
            P[row][2] = fma2(e2.y, mnb, P[row][2]);
            P[row][3] = fma2(e3.x, mna, P[row][3]);
            P[row][3] = fma2(e3.y, mnb, P[row][3]);
        }
        #pragma unroll
        for (int row = 0; row < 4; row++) vc[row] = vn[row];
    }

    // reduce packed accumulators and write m_read
    #pragma unroll
    for (int row = 0; row < 4; row++) {
        #pragma unroll
        for (int r = 0; r < R; r++) {
            float s = hadd2(P[row][r]);
            #pragma unroll
            for (int o2 = 16; o2; o2 >>= 1)
                s += __shfl_xor_sync(0xffffffffu, s, o2);
            if (lane == 0)
                mread[(size_t)b*R*W + r*W + w0 + row] = s / Zr[r];
        }
    }
}

// ===================== launch =====================
extern "C" void kernel_launch(void* const* d_in, const int* in_sizes, int n_in,
                              void* d_out, int out_size) {
    const float* k_r   = (const float*)d_in[0];
    const float* m_t   = (const float*)d_in[1];
    const float* e_t   = (const float*)d_in[2];
    const float* m_er  = (const float*)d_in[3];
    const float* mem   = (const float*)d_in[4];
    const float* gW    = (const float*)d_in[5];
    const float* gb    = (const float*)d_in[6];
    const float* oW    = (const float*)d_in[7];
    const float* ob    = (const float*)d_in[8];

    float* out   = (float*)d_out;
    float* mread = out;               // (BS,R,W)
    float* Mnew  = out + OFF_MNEW;    // (BS,W,N)
    float* rwt   = out + OFF_RWT;     // (BS,R,N)

    k1_prep    <<<dim3(8,   BS), 256>>>(k_r, m_t, e_t, m_er, gW, gb, oW, ob);
    k23_moments<<<dim3(CHW, BS), 256>>>(mem);
    k4x_stream <<<dim3(8,   BS), 256>>>(mem, Mnew, rwt, mread);
}

// round 16
// speedup vs baseline: 1.0221x; 1.0007x over previous
#include <cuda_runtime.h>
#include <math.h>

// Fixed shapes for BlurredMem_61950608278069
#define BS 128
#define W  256
#define N  2048
#define R  4
#define EPSF 1e-8f
#define CHW 4                 // k23 n-chunks (512 n per block, 2 per thread)

// Output layout: m_read (BS,R,W) | M_new (BS,W,N) | read_wt (BS,R,N)
#define OFF_MNEW (BS*R*W)
#define OFF_RWT  (BS*R*W + BS*W*N)

typedef unsigned long long u64;

// -------- packed f32x2 helpers (Blackwell; ptxas never auto-fuses these) ---
__device__ __forceinline__ u64 pk2(float v) {
    u64 r; asm("mov.b64 %0, {%1,%1};" : "=l"(r) : "f"(v)); return r;
}
__device__ __forceinline__ u64 fma2(u64 a, u64 b, u64 c) {
    u64 d; asm("fma.rn.f32x2 %0, %1, %2, %3;" : "=l"(d) : "l"(a), "l"(b), "l"(c));
    return d;
}
__device__ __forceinline__ u64 mul2(u64 a, u64 b) {
    u64 d; asm("mul.rn.f32x2 %0, %1, %2;" : "=l"(d) : "l"(a), "l"(b));
    return d;
}
__device__ __forceinline__ float2 up2(u64 p) {
    float2 f; asm("mov.b64 {%0, %1}, %2;" : "=f"(f.x), "=f"(f.y) : "l"(p));
    return f;
}
__device__ __forceinline__ float hadd2(u64 p) { float2 f = up2(p); return f.x + f.y; }

// fast tanh: 1 - 2/(e^{2x}+1); rel err ~1e-6, exact saturation
__device__ __forceinline__ float ftanh(float x) {
    const float e = __expf(2.f * x);
    return 1.f - 2.f / (e + 1.f);
}

union V2 { ulonglong2 u; float4 f; };

// -------- scratch (device globals) --------
__device__ float  g_wk[BS*W];        // unnormalized write key (relu'd)
__device__ float2 g_wmer[BS*W];      // (write_m, erase_vec)
__device__ float4 g_kn4[BS*W];       // normalized read keys (r packed)
__device__ float  g_scal[BS*8];      // {Swm, C0..C3}
__device__ float  g_Zw_part[BS*CHW]; // per-block partial Zw
__device__ float  g_wwt[BS*N];       // normalized write weights
__device__ float  g_rexp[BS*R*N];    // unnormalized read weights (scratch)
__device__ float4 g_Zr_part[BS*CHW]; // per-chunk Zr (4 heads)
__device__ int    g_cnt[BS];         // per-batch barrier counters (k1 zeroes)

// -------- block reduction: warp shuffles + one smem pass (256 threads) ----
template<int NV>
__device__ __forceinline__ void blk_reduce_sum(float (&v)[NV], float* sbuf) {
    const int lane = threadIdx.x & 31, wid = threadIdx.x >> 5;
    #pragma unroll
    for (int i = 0; i < NV; i++) {
        float x = v[i];
        #pragma unroll
        for (int o = 16; o; o >>= 1) x += __shfl_xor_sync(0xffffffffu, x, o);
        if (lane == 0) sbuf[i*8 + wid] = x;
    }
    __syncthreads();
    #pragma unroll
    for (int i = 0; i < NV; i++) {
        float s = 0.f;
        #pragma unroll
        for (int j = 0; j < 8; j++) s += sbuf[i*8 + j];
        v[i] = s;
    }
    __syncthreads();
}

// -------- 4-block batch barrier: release + counter, t0 spins, acquire -----
__device__ __forceinline__ void team_sync4(int* cnt) {
    __syncthreads();
    __threadfence();
    if (threadIdx.x == 0) {
        atomicAdd(cnt, 1);
        volatile int* vc = (volatile int*)cnt;
        while (*vc < CHW) __nanosleep(64);
    }
    __syncthreads();
    __threadfence();
}

// ===================== K1: per-batch prep (grid 8 x BS) =====================
// Asymmetric: block 0 of each batch does the full 11-value reduction + table
// writes; blocks 1-7 compute only {wm, me, gate} (1-value reduction), then
// all blocks do their 32-row MLP slice.
__global__ void k1_prep(const float* __restrict__ k_r, const float* __restrict__ m_t,
                        const float* __restrict__ e_t, const float* __restrict__ m_er,
                        const float* __restrict__ gW,  const float* __restrict__ gb,
                        const float* __restrict__ oW,  const float* __restrict__ ob) {
    __shared__ float sbuf[96];
    __shared__ __align__(16) float s_cat[2*W];
    const int b = blockIdx.y, t = threadIdx.x;

    if (blockIdx.x == 0 && t == 0) g_cnt[b] = 0;   // reset k23 barrier counter

    const float wm = ftanh(m_t[b*W + t]);
    const float me = m_er[b*W + t];

    if (blockIdx.x == 0) {
        const float ex = __expf(e_t[b*W + t]);      // erase softmax, no max pass
        float kv[R];
        #pragma unroll
        for (int r = 0; r < R; r++) kv[r] = ftanh(k_r[(b*R + r)*W + t]);

        float v[11];
        v[0] = ex;
        v[1] = wm * gW[t] + me * gW[W + t];
        #pragma unroll
        for (int r = 0; r < R; r++) v[2+r] = kv[r] * kv[r];
        v[6] = wm * wm;
        #pragma unroll
        for (int r = 0; r < R; r++) v[7+r] = kv[r] * wm;
        blk_reduce_sum<11>(v, sbuf);

        const float g = 1.f / (1.f + __expf(-(v[1] + gb[0])));
        s_cat[t]     = g * wm;
        s_cat[W + t] = (1.f - g) * me;

        g_wmer[b*W + t] = make_float2(wm, ex / v[0]);
        float kn[R];
        #pragma unroll
        for (int r = 0; r < R; r++) kn[r] = kv[r] / (sqrtf(v[2+r]) + EPSF);
        g_kn4[b*W + t] = make_float4(kn[0], kn[1], kn[2], kn[3]);
        if (t == 0) {
            g_scal[b*8 + 0] = v[6];
            #pragma unroll
            for (int r = 0; r < R; r++)
                g_scal[b*8 + 1 + r] = v[7+r] / (sqrtf(v[2+r]) + EPSF);
        }
    } else {
        float v[1] = { wm * gW[t] + me * gW[W + t] };
        blk_reduce_sum<1>(v, sbuf);
        const float g = 1.f / (1.f + __expf(-(v[0] + gb[0])));
        s_cat[t]     = g * wm;
        s_cat[W + t] = (1.f - g) * me;
    }
    __syncthreads();

    // MLP: 32 rows per block, 8 threads per row
    const int o = blockIdx.x * 32 + (t >> 3);
    const int p = t & 7;
    const float4* orow4 = (const float4*)(oW + (size_t)o * 2 * W);
    const float4* sc4   = (const float4*)s_cat;
    float acc = 0.f;
    #pragma unroll
    for (int i = 0; i < 16; i++) {
        const int j = 8*i + p;
        float4 ow = orow4[j], sc = sc4[j];
        acc += ow.x*sc.x + ow.y*sc.y + ow.z*sc.z + ow.w*sc.w;
    }
    acc += __shfl_xor_sync(0xffffffffu, acc, 1);
    acc += __shfl_xor_sync(0xffffffffu, acc, 2);
    acc += __shfl_xor_sync(0xffffffffu, acc, 4);
    if (p == 0) g_wk[b*W + o] = fmaxf(acc + ob[o], 0.f);
}

// ===================== K23: moments + (barrier) + read weights =============
// Thread owns 2 adjacent columns; moments stay in registers. After the main
// loop, the batch's 4 blocks sync on a counter; each then computes wwt/e_r
// locally and writes only g_wwt + g_rexp + Zr partials. No moment planes.
__global__ void
k23_moments(const float* __restrict__ mem) {
    __shared__ __align__(16) ulonglong2 s_knA[W];   // {dup(kn0), dup(kn1)}
    __shared__ __align__(16) ulonglong2 s_knB[W];   // {dup(kn2), dup(kn3)}
    __shared__ __align__(16) ulonglong2 s_ewm[W];   // {dup(er),  dup(wm)}
    __shared__ u64  s_wkn[W];                       // dup(wkn)
    __shared__ float sbuf[32];
    const int b = blockIdx.y, t = threadIdx.x;

    // prologue: t == w  (write-key normalization)
    const float wk = g_wk[b*W + t];
    float v1[1] = { wk * wk };
    blk_reduce_sum<1>(v1, sbuf);
    const float wkn = wk / (sqrtf(v1[0]) + EPSF);
    const float2 me = g_wmer[b*W + t];              // (wm, er)
    const float4 kn = g_kn4[b*W + t];
    s_knA[t] = make_ulonglong2(pk2(kn.x), pk2(kn.y));
    s_knB[t] = make_ulonglong2(pk2(kn.z), pk2(kn.w));
    s_ewm[t] = make_ulonglong2(pk2(me.y), pk2(me.x));
    s_wkn[t] = pk2(wkn);
    __syncthreads();

    const int n0 = blockIdx.x * 512 + 2 * t;
    const u64* mp = (const u64*)(mem + (size_t)b * W * N + n0);

    u64 S0 = 0, S1 = 0, S2 = 0, T0 = 0, T1 = 0, dW = 0;
    u64 A0 = 0, A1 = 0, A2 = 0, A3 = 0;
    u64 B0 = 0, B1 = 0, B2 = 0, B3 = 0;

    u64 cur[8], nxt[8];
    #pragma unroll
    for (int i = 0; i < 8; i++) cur[i] = mp[(size_t)i * (N/2)];

    #pragma unroll 4
    for (int wb = 0; wb < W; wb += 8) {
        const u64* mpn = mp + (size_t)(wb + 8) * (N/2);
        if (wb + 8 < W) {
            #pragma unroll
            for (int i = 0; i < 8; i++) nxt[i] = mpn[(size_t)i * (N/2)];
        }
        #pragma unroll
        for (int i = 0; i < 8; i++) {
            const int w = wb + i;
            const u64 v = cur[i];
            const ulonglong2 ka = s_knA[w];
            const ulonglong2 kb = s_knB[w];
            const ulonglong2 ew = s_ewm[w];         // {er2, wm2}
            const u64 u = mul2(ew.x, v);            // er * v
            S0 = fma2(v, v, S0);
            S1 = fma2(u, v, S1);
            S2 = fma2(u, u, S2);
            dW = fma2(s_wkn[w], v, dW);
            T0 = fma2(ew.y, v, T0);
            T1 = fma2(ew.y, u, T1);
            A0 = fma2(ka.x, v, A0);  A1 = fma2(ka.y, v, A1);
            A2 = fma2(kb.x, v, A2);  A3 = fma2(kb.y, v, A3);
            B0 = fma2(ka.x, u, B0);  B1 = fma2(ka.y, u, B1);
            B2 = fma2(kb.x, u, B2);  B3 = fma2(kb.y, u, B3);
        }
        if (wb + 8 < W) {
            #pragma unroll
            for (int i = 0; i < 8; i++) cur[i] = nxt[i];
        }
    }

    // ---- fold scalars; everything stays in registers ----
    const float Swm = g_scal[b*8 + 0];
    const float Cs[R] = { g_scal[b*8+1], g_scal[b*8+2],
                          g_scal[b*8+3], g_scal[b*8+4] };

    const float2 sa = up2(S0), dw = up2(dW);
    const float2 s1 = up2(S1), s2 = up2(S2);
    const float2 t0 = up2(T0), t1 = up2(T1);
    float2 ew2;
    ew2.x = __expf(-dw.x / (sqrtf(sa.x) + EPSF));
    ew2.y = __expf(-dw.y / (sqrtf(sa.y) + EPSF));
    const float2 SB = make_float2(t0.x - s1.x, t0.y - s1.y);
    const float2 SC = make_float2(s2.x - 2.f*t1.x + Swm,
                                  s2.y - 2.f*t1.y + Swm);
    const float2 Af[R] = { up2(A0), up2(A1), up2(A2), up2(A3) };
    const float2 Bf[R] = { up2(B0), up2(B1), up2(B2), up2(B3) };

    // partial Zw, then batch barrier (4 sibling blocks)
    float z[1] = { ew2.x + ew2.y };
    blk_reduce_sum<1>(z, sbuf);
    if (t == 0) g_Zw_part[b*CHW + blockIdx.x] = z[0];
    team_sync4(&g_cnt[b]);

    float Zw = 0.f;
    #pragma unroll
    for (int k = 0; k < CHW; k++) Zw += g_Zw_part[b*CHW + k];
    const float iZw = 1.f / Zw;

    // wwt + read-weight exponentials for this thread's 2 columns
    const float2 wwt2 = make_float2(ew2.x * iZw, ew2.y * iZw);
    *(float2*)&g_wwt[(size_t)b*N + n0] = wwt2;

    const float nm2x = fmaf(wwt2.x, fmaf(wwt2.x, SC.x, 2.f*SB.x), sa.x);
    const float nm2y = fmaf(wwt2.y, fmaf(wwt2.y, SC.y, 2.f*SB.y), sa.y);
    const float invx = 1.f / (sqrtf(fmaxf(nm2x, 0.f)) + EPSF);
    const float invy = 1.f / (sqrtf(fmaxf(nm2y, 0.f)) + EPSF);

    float zr[R];
    #pragma unroll
    for (int r = 0; r < R; r++) {
        const float ex2 = __expf(fmaf(wwt2.x, Cs[r] - Bf[r].x, Af[r].x) * invx);
        const float ey2 = __expf(fmaf(wwt2.y, Cs[r] - Bf[r].y, Af[r].y) * invy);
        *(float2*)&g_rexp[((size_t)b*R + r)*N + n0] = make_float2(ex2, ey2);
        zr[r] = ex2 + ey2;
    }
    blk_reduce_sum<R>(zr, sbuf);
    if (t == 0)
        g_Zr_part[b*CHW + blockIdx.x] = make_float4(zr[0], zr[1], zr[2], zr[3]);
}

// ===================== K4x: M_new stream + m_read + normalized rwt ========
// grid (8, BS); warp owns 4 w-rows. Stages wwt + e (full batch) in smem;
// writes its normalized rwt output slice; streams mem, writes M_new,
// accumulates P[row][r] += e_r * mn in packed registers.
__global__ void __launch_bounds__(256, 2)
k4x_stream(const float* __restrict__ mem, float* __restrict__ Mnew,
           float* __restrict__ rwt, float* __restrict__ mread) {
    __shared__ __align__(16) float s_wwt[N];      // 8 KB
    __shared__ __align__(16) float s_e[R][N];     // 32 KB
    const int b = blockIdx.y, c = blockIdx.x;
    const int t = threadIdx.x, lane = t & 31, wi = t >> 5;

    float Zr[R] = {0,0,0,0};
    #pragma unroll
    for (int k = 0; k < CHW; k++) {
        float4 z = g_Zr_part[b*CHW + k];
        Zr[0] += z.x; Zr[1] += z.y; Zr[2] += z.z; Zr[3] += z.w;
    }

    #pragma unroll
    for (int k = 0; k < 2; k++) {
        const int idx = t + k * 256;
        ((float4*)s_wwt)[idx] = ((const float4*)(g_wwt + (size_t)b*N))[idx];
        #pragma unroll
        for (int r = 0; r < R; r++)
            ((float4*)&s_e[r][0])[idx] =
                ((const float4*)(g_rexp + ((size_t)b*R + r)*N))[idx];
    }
    __syncthreads();

    // write this block's normalized rwt output slice (256 of 2048 float4)
    {
        const int idx = c * 256 + t;
        const int r = idx >> 9;
        const float s = 1.f / Zr[r];
        float4 v = ((const float4*)s_e)[idx];
        v.x *= s; v.y *= s; v.z *= s; v.w *= s;
        ((float4*)(rwt + (size_t)b * R * N))[idx] = v;
    }

    const int w0 = c * 32 + wi * 4;
    u64 wm2[4], ner2[4];
    #pragma unroll
    for (int row = 0; row < 4; row++) {
        float2 me = g_wmer[b*W + w0 + row];
        wm2[row]  = pk2(me.x);
        ner2[row] = pk2(-me.y);
    }

    const ulonglong2* mp = (const ulonglong2*)(mem  + ((size_t)b*W + w0) * N);
    ulonglong2*       op = (ulonglong2*)(Mnew + ((size_t)b*W + w0) * N);
    const ulonglong2* sw = (const ulonglong2*)s_wwt;
    const ulonglong2* se0 = (const ulonglong2*)&s_e[0][0];
    const ulonglong2* se1 = (const ulonglong2*)&s_e[1][0];
    const ulonglong2* se2 = (const ulonglong2*)&s_e[2][0];
    const ulonglong2* se3 = (const ulonglong2*)&s_e[3][0];

    u64 P[4][R] = {};
    ulonglong2 vc[4];
    #pragma unroll
    for (int row = 0; row < 4; row++) vc[row] = mp[lane + row * (N/4)];

    #pragma unroll 2
    for (int k = 0; k < 16; k++) {
        const int idx  = lane + k * 32;
        const int nidx = (k < 15) ? idx + 32 : idx;
        ulonglong2 vn[4];
        #pragma unroll
        for (int row = 0; row < 4; row++) vn[row] = mp[nidx + row * (N/4)];

        const ulonglong2 ww = sw[idx];
        const ulonglong2 e0 = se0[idx], e1 = se1[idx];
        const ulonglong2 e2 = se2[idx], e3 = se3[idx];
        #pragma unroll
        for (int row = 0; row < 4; row++) {
            const ulonglong2 v = vc[row];
            // mn = wm*ww + (-er)*(v*ww) + v
            const u64 mna = fma2(wm2[row], ww.x, fma2(ner2[row], mul2(v.x, ww.x), v.x));
            const u64 mnb = fma2(wm2[row], ww.y, fma2(ner2[row], mul2(v.y, ww.y), v.y));
            V2 st; st.u = make_ulonglong2(mna, mnb);
            __stcs((float4*)&op[idx + row * (N/4)], st.f);
            P[row][0] = fma2(e0.x, mna, P[row][0]);
            P[row][0] = fma2(e0.y, mnb, P[row][0]);
            P[row][1] = fma2(e1.x, mna, P[row][1]);
            P[row][1] = fma2(e1.y, mnb, P[row][1]);
            P[row][2] = fma2(e2.x, mna, P[row][2]);
            P[row][2] = fma2(e2.y, mnb, P[row][2]);
            P[row][3] = fma2(e3.x, mna, P[row][3]);
            P[row][3] = fma2(e3.y, mnb, P[row][3]);
        }
        #pragma unroll
        for (int row = 0; row < 4; row++) vc[row] = vn[row];
    }

    // reduce packed accumulators and write m_read
    #pragma unroll
    for (int row = 0; row < 4; row++) {
        #pragma unroll
        for (int r = 0; r < R; r++) {
            float s = hadd2(P[row][r]);
            #pragma unroll
            for (int o2 = 16; o2; o2 >>= 1)
                s += __shfl_xor_sync(0xffffffffu, s, o2);
            if (lane == 0)
                mread[(size_t)b*R*W + r*W + w0 + row] = s / Zr[r];
        }
    }
}

// ===================== launch =====================
extern "C" void kernel_launch(void* const* d_in, const int* in_sizes, int n_in,
                              void* d_out, int out_size) {
    const float* k_r   = (const float*)d_in[0];
    const float* m_t   = (const float*)d_in[1];
    const float* e_t   = (const float*)d_in[2];
    const float* m_er  = (const float*)d_in[3];
    const float* mem   = (const float*)d_in[4];
    const float* gW    = (const float*)d_in[5];
    const float* gb    = (const float*)d_in[6];
    const float* oW    = (const float*)d_in[7];
    const float* ob    = (const float*)d_in[8];

    float* out   = (float*)d_out;
    float* mread = out;               // (BS,R,W)
    float* Mnew  = out + OFF_MNEW;    // (BS,W,N)
    float* rwt   = out + OFF_RWT;     // (BS,R,N)

    k1_prep    <<<dim3(8,   BS), 256>>>(k_r, m_t, e_t, m_er, gW, gb, oW, ob);
    k23_moments<<<dim3(CHW, BS), 256>>>(mem);
    k4x_stream <<<dim3(8,   BS), 256>>>(mem, Mnew, rwt, mread);
}